// round 1
// baseline (speedup 1.0000x reference)
#include <cuda_runtime.h>
#include <math.h>

#define NROWS 12288
#define DIM   128
#define BSZ   4096
#define NB    32      // 4096 / 128 tiles per dim
#define BM    128
#define BN    128
#define KC    32      // k-chunk staged in smem
#define SA    33      // padded smem stride (floats)

// Scratch (device globals; no allocation allowed)
__device__ float g_xn[NROWS * DIM];   // normalized input
__device__ float g_s[5][BSZ];         // row sums per gemm (xx, yy, xy, ax, ay)
__device__ float g_c[2][BSZ];         // col sums for ax, ay (== s_zx, s_zy)
__device__ float g_d[5][BSZ];         // diagonals per gemm

// --------------------------------------------------------------------------
__global__ void zero_kernel() {
    int i = blockIdx.x * blockDim.x + threadIdx.x;
    if (i < 5 * BSZ) ((float*)g_s)[i] = 0.0f;
    if (i < 2 * BSZ) ((float*)g_c)[i] = 0.0f;
    if (i < 5 * BSZ) ((float*)g_d)[i] = 0.0f;
}

// One warp per row: sum of squares -> rsqrt -> scaled write.
__global__ void normalize_kernel(const float* __restrict__ x) {
    int row  = blockIdx.x * (blockDim.x >> 5) + (threadIdx.x >> 5);
    int lane = threadIdx.x & 31;
    if (row >= NROWS) return;
    float4 v = ((const float4*)(x + row * DIM))[lane];
    float ss = v.x * v.x + v.y * v.y + v.z * v.z + v.w * v.w;
    #pragma unroll
    for (int o = 16; o; o >>= 1) ss += __shfl_xor_sync(0xffffffffu, ss, o);
    float inv = rsqrtf(fmaxf(ss, 1e-24f));
    float4 o4 = make_float4(v.x * inv, v.y * inv, v.z * inv, v.w * inv);
    ((float4*)(g_xn + row * DIM))[lane] = o4;
}

__device__ __forceinline__ float ex2_fast(float a) {
    float r;
    asm("ex2.approx.ftz.f32 %0, %1;" : "=f"(r) : "f"(a));
    return r;
}

// z: 0=xx(sym) 1=yy(sym) 2=xy 3=xz(ax) 4=yz(ay)
__global__ void __launch_bounds__(256, 2) gemm_kernel() {
    const int z  = blockIdx.z;
    const int by = blockIdx.y, bx = blockIdx.x;
    const bool sym = (z < 2);
    if (sym && bx < by) return;   // symmetric: upper triangle only

    const int aoffs[5] = {0, 1, 0, 0, 1};
    const int boffs[5] = {0, 1, 1, 2, 2};
    const float* __restrict__ A = g_xn + aoffs[z] * BSZ * DIM;
    const float* __restrict__ B = g_xn + boffs[z] * BSZ * DIM;
    float* srow = g_s[z];
    float* scol = (z == 3) ? g_c[0] : (z == 4) ? g_c[1] : nullptr;
    float* dd   = g_d[z];

    __shared__ float As[BM * SA];
    __shared__ float Bs[BN * SA];
    __shared__ float rs[BM];
    __shared__ float cs[BN];

    const int tid = threadIdx.x;
    const int tx  = tid & 15, ty = tid >> 4;
    const int rowA0 = by * BM;
    const int rowB0 = bx * BN;

    float acc[8][8];
    #pragma unroll
    for (int i = 0; i < 8; i++)
        #pragma unroll
        for (int j = 0; j < 8; j++) acc[i][j] = 0.0f;

    for (int kc = 0; kc < DIM; kc += KC) {
        // Stage A & B chunks: 128 rows x 32 floats each (conflict-free STS).
        #pragma unroll
        for (int it = 0; it < 4; it++) {
            int f  = tid + 256 * it;
            int r  = f >> 3;
            int kq = f & 7;
            float4 v = *(const float4*)(A + (rowA0 + r) * DIM + kc + kq * 4);
            float* p = &As[r * SA + kq * 4];
            p[0] = v.x; p[1] = v.y; p[2] = v.z; p[3] = v.w;
            float4 w = *(const float4*)(B + (rowB0 + r) * DIM + kc + kq * 4);
            float* q = &Bs[r * SA + kq * 4];
            q[0] = w.x; q[1] = w.y; q[2] = w.z; q[3] = w.w;
        }
        __syncthreads();
        #pragma unroll
        for (int k = 0; k < KC; k++) {
            float af[8], bf[8];
            #pragma unroll
            for (int i = 0; i < 8; i++) {
                int r = (i < 4) ? (ty * 4 + i) : (64 + ty * 4 + (i - 4));
                af[i] = As[r * SA + k];
            }
            #pragma unroll
            for (int j = 0; j < 8; j++)
                bf[j] = Bs[(tx + 16 * j) * SA + k];
            #pragma unroll
            for (int i = 0; i < 8; i++)
                #pragma unroll
                for (int j = 0; j < 8; j++)
                    acc[i][j] = fmaf(af[i], bf[j], acc[i][j]);
        }
        __syncthreads();
    }

    // Epilogue: exp + tile reductions (row sums, col sums, diagonal).
    if (tid < BM) { rs[tid] = 0.0f; cs[tid] = 0.0f; }
    __syncthreads();

    const float scale = 14.4269504088896340f;   // (1/temp) * log2(e), temp = 0.1
    float rpart[8], cpart[8];
    #pragma unroll
    for (int i = 0; i < 8; i++) { rpart[i] = 0.0f; cpart[i] = 0.0f; }

    #pragma unroll
    for (int i = 0; i < 8; i++) {
        int r  = (i < 4) ? (ty * 4 + i) : (64 + ty * 4 + (i - 4));
        int gr = rowA0 + r;
        #pragma unroll
        for (int j = 0; j < 8; j++) {
            int c  = tx + 16 * j;
            int gc = rowB0 + c;
            float e = ex2_fast(acc[i][j] * scale);
            rpart[i] += e;
            cpart[j] += e;
            if (by == bx && gr == gc) dd[gr] = e;
        }
    }
    #pragma unroll
    for (int i = 0; i < 8; i++) {
        int r = (i < 4) ? (ty * 4 + i) : (64 + ty * 4 + (i - 4));
        atomicAdd(&rs[r], rpart[i]);
    }
    #pragma unroll
    for (int j = 0; j < 8; j++)
        atomicAdd(&cs[tx + 16 * j], cpart[j]);
    __syncthreads();

    if (tid < BM) {
        atomicAdd(&srow[rowA0 + tid], rs[tid]);
        if (scol) atomicAdd(&scol[rowB0 + tid], cs[tid]);
        // symmetric matrices: column partials of the skipped lower-triangle
        // blocks are the row sums of the transposed entries.
        if (sym && bx > by) atomicAdd(&srow[rowB0 + tid], cs[tid]);
    }
}

__global__ void loss_kernel(float* __restrict__ out) {
    __shared__ float red[256];
    float acc = 0.0f;
    for (int i = threadIdx.x; i < BSZ; i += blockDim.x) {
        float d0 = g_d[0][i], s0 = g_s[0][i];
        float d1 = g_d[1][i], s1 = g_s[1][i];
        float d2 = g_d[2][i], s2 = g_s[2][i];
        float d3 = g_d[3][i], s3 = g_s[3][i];
        float d4 = g_d[4][i], s4 = g_s[4][i];
        float c0 = g_c[0][i], c1 = g_c[1][i];
        float denom = (s2 - d2) + (s0 - d0) + (s1 - d1);
        float t = -2.0f * logf(d2 / denom)
                  - logf(d3 / (s3 - d3)) - logf(d4 / (s4 - d4))
                  - logf(d3 / (c0 - d3)) - logf(d4 / (c1 - d4));
        acc += t;
    }
    red[threadIdx.x] = acc;
    __syncthreads();
    for (int s = 128; s; s >>= 1) {
        if (threadIdx.x < s) red[threadIdx.x] += red[threadIdx.x + s];
        __syncthreads();
    }
    if (threadIdx.x == 0) out[0] = red[0] * (1.0f / BSZ);
}

// --------------------------------------------------------------------------
extern "C" void kernel_launch(void* const* d_in, const int* in_sizes, int n_in,
                              void* d_out, int out_size) {
    const float* x = (const float*)d_in[0];
    (void)in_sizes; (void)n_in; (void)out_size;

    zero_kernel<<<(5 * BSZ + 255) / 256, 256>>>();
    normalize_kernel<<<NROWS / 8, 256>>>(x);
    dim3 grid(NB, NB, 5);
    gemm_kernel<<<grid, 256>>>();
    loss_kernel<<<1, 256>>>((float*)d_out);
}

// round 3
// speedup vs baseline: 3.9348x; 3.9348x over previous
#include <cuda_runtime.h>
#include <cuda_bf16.h>
#include <cstdint>
#include <math.h>

#define NROWS 12288
#define DIM   128
#define BSZ   4096
#define KHL   256          // [hi|lo] concat-K (symmetric; lo*lo term is a bonus)
#define BM    128
#define BN    128
#define NT    32           // 4096 / 128
#define SYMT  528          // 32*33/2
#define NBLK  (2*SYMT + 3*NT*NT)   // 4128

// ---- device scratch --------------------------------------------------------
__device__ __align__(16) __nv_bfloat16 g_n[NROWS * KHL];  // [hi(128) | lo(128)]
__device__ float g_s[5][BSZ];   // row sums (xx, yy, xy, xz, yz)
__device__ float g_c[2][BSZ];   // col sums of xz, yz (== s_zx, s_zy)
__device__ float g_d[5][BSZ];   // diagonals

// ---- helpers ----------------------------------------------------------------
__device__ __forceinline__ uint32_t smem_u32(const void* p) {
    uint32_t a;
    asm("{ .reg .u64 t; cvta.to.shared.u64 t, %1; cvt.u32.u64 %0, t; }"
        : "=r"(a) : "l"(p));
    return a;
}
__device__ __forceinline__ float ex2f(float a) {
    float r; asm("ex2.approx.ftz.f32 %0, %1;" : "=f"(r) : "f"(a)); return r;
}
__device__ __forceinline__ void cp16(uint32_t dst, const void* src) {
    asm volatile("cp.async.cg.shared.global [%0], [%1], 16;"
                 :: "r"(dst), "l"(src) : "memory");
}
__device__ __forceinline__ void cp_commit() {
    asm volatile("cp.async.commit_group;" ::: "memory");
}
template <int N>
__device__ __forceinline__ void cp_wait() {
    asm volatile("cp.async.wait_group %0;" :: "n"(N) : "memory");
}
__device__ __forceinline__ void ldsm4(uint32_t* r, uint32_t a) {
    asm volatile("ldmatrix.sync.aligned.m8n8.x4.shared.b16 {%0,%1,%2,%3}, [%4];"
                 : "=r"(r[0]), "=r"(r[1]), "=r"(r[2]), "=r"(r[3]) : "r"(a));
}
__device__ __forceinline__ void mma16816(float* c, const uint32_t* a, const uint32_t* b) {
    asm volatile(
        "mma.sync.aligned.m16n8k16.row.col.f32.bf16.bf16.f32 "
        "{%0,%1,%2,%3}, {%4,%5,%6,%7}, {%8,%9}, {%0,%1,%2,%3};"
        : "+f"(c[0]), "+f"(c[1]), "+f"(c[2]), "+f"(c[3])
        : "r"(a[0]), "r"(a[1]), "r"(a[2]), "r"(a[3]), "r"(b[0]), "r"(b[1]));
}

// ---- small kernels ----------------------------------------------------------
__global__ void zero_kernel() {
    int i = blockIdx.x * blockDim.x + threadIdx.x;
    if (i < 5 * BSZ) ((float*)g_s)[i] = 0.0f;
    if (i < 2 * BSZ) ((float*)g_c)[i] = 0.0f;
}

__global__ void normalize_split_kernel(const float* __restrict__ x) {
    int row  = blockIdx.x * 8 + (threadIdx.x >> 5);
    int lane = threadIdx.x & 31;
    float4 v = ((const float4*)(x + (size_t)row * DIM))[lane];
    float ss = fmaf(v.x, v.x, fmaf(v.y, v.y, fmaf(v.z, v.z, v.w * v.w)));
    #pragma unroll
    for (int o = 16; o; o >>= 1) ss += __shfl_xor_sync(0xffffffffu, ss, o);
    float inv = rsqrtf(fmaxf(ss, 1e-24f));
    float xv[4] = {v.x * inv, v.y * inv, v.z * inv, v.w * inv};

    __nv_bfloat16 hi[4], lo[4];
    #pragma unroll
    for (int c = 0; c < 4; c++) {
        hi[c] = __float2bfloat16(xv[c]);
        lo[c] = __float2bfloat16(xv[c] - __bfloat162float(hi[c]));
    }
    __nv_bfloat162 h01(hi[0], hi[1]), h23(hi[2], hi[3]);
    __nv_bfloat162 l01(lo[0], lo[1]), l23(lo[2], lo[3]);
    size_t base = (size_t)row * KHL + lane * 4;
    *(uint2*)(g_n + base)       = make_uint2(*(uint32_t*)&h01, *(uint32_t*)&h23);
    *(uint2*)(g_n + base + 128) = make_uint2(*(uint32_t*)&l01, *(uint32_t*)&l23);
}

// ---- main GEMM + fused exp/reduce ------------------------------------------
// dyn smem: A0 16K | B0 16K | A1 16K | B1 16K | rs 512 | cs 512
#define SM_A(b)   ((b) * 32768)
#define SM_B(b)   ((b) * 32768 + 16384)
#define SM_RS     65536
#define SM_CS     (65536 + 512)
#define SMEM_BYTES (65536 + 1024)

__global__ void __launch_bounds__(256, 2) gemm_kernel() {
    extern __shared__ char sbp[];
    const uint32_t sb = smem_u32(sbp);

    const int tid = threadIdx.x, wid = tid >> 5, lane = tid & 31;

    // block -> (z, by, bx)
    int idx = blockIdx.x;
    int z, by, bx;
    if (idx < 2 * SYMT) {
        z = idx < SYMT ? 0 : 1;
        int t = idx - z * SYMT, r = 0;
        while (t >= NT - r) { t -= NT - r; r++; }
        by = r; bx = r + t;                       // upper triangle incl diag
    } else {
        int t = idx - 2 * SYMT;
        z = 2 + t / (NT * NT); t %= NT * NT;
        by = t / NT; bx = t % NT;
    }
    const int aoffs[5] = {0, 1, 0, 0, 1};
    const int boffs[5] = {0, 1, 1, 2, 2};
    const bool sym      = (z < 2);
    const bool needCol  = (z >= 3) || (sym && bx > by);
    const bool needDiag = (by == bx);

    const char* Agp = (const char*)g_n + (size_t)(aoffs[z] * BSZ + by * BM) * (KHL * 2);
    const char* Bgp = (const char*)g_n + (size_t)(boffs[z] * BSZ + bx * BN) * (KHL * 2);

    // ---- staging: 128 rows x 64 bf16 (128B) per matrix per stage -----------
    const int lrow = tid >> 3, lseg = tid & 7;          // covers 32 rows/iter
    auto stage = [&](int s, int b) {
        #pragma unroll
        for (int it = 0; it < 4; it++) {
            int row = lrow + it * 32;
            uint32_t off = (uint32_t)(row * 128 + lseg * 16);
            uint32_t sw  = off ^ ((row & 7) << 4);
            size_t go = (size_t)row * 512 + s * 128 + lseg * 16;
            cp16(sb + SM_A(b) + sw, Agp + go);
            cp16(sb + SM_B(b) + sw, Bgp + go);
        }
        cp_commit();
    };

    const int warp_m = wid >> 2, warp_n = wid & 3;      // 2 x 4 warp grid
    const int rowT = warp_m * 64, colT = warp_n * 32;
    const int lr16 = lane & 15, lcs = (lane >> 4) * 16; // ldmatrix addressing

    float acc[4][4][4];
    #pragma unroll
    for (int i = 0; i < 4; i++)
        #pragma unroll
        for (int j = 0; j < 4; j++)
            #pragma unroll
            for (int e = 0; e < 4; e++) acc[i][j][e] = 0.0f;

    auto compute = [&](int b) {
        #pragma unroll
        for (int k16 = 0; k16 < 4; k16++) {
            uint32_t af[4][4], bf[2][4];
            #pragma unroll
            for (int mt = 0; mt < 4; mt++) {
                int row = rowT + mt * 16 + lr16;
                uint32_t off = (uint32_t)(row * 128 + k16 * 32 + lcs);
                ldsm4(af[mt], sb + SM_A(b) + (off ^ ((row & 7) << 4)));
            }
            #pragma unroll
            for (int nb = 0; nb < 2; nb++) {
                int row = colT + nb * 16 + lr16;
                uint32_t off = (uint32_t)(row * 128 + k16 * 32 + lcs);
                ldsm4(bf[nb], sb + SM_B(b) + (off ^ ((row & 7) << 4)));
            }
            #pragma unroll
            for (int mt = 0; mt < 4; mt++)
                #pragma unroll
                for (int nt = 0; nt < 4; nt++) {
                    uint32_t bb[2] = {bf[nt >> 1][nt & 1], bf[nt >> 1][(nt & 1) + 2]};
                    mma16816(acc[mt][nt], af[mt], bb);
                }
        }
    };

    // ---- pipelined mainloop over 4 K-chunks ---------------------------------
    stage(0, 0);
    stage(1, 1);
    cp_wait<1>(); __syncthreads();
    compute(0);   __syncthreads();
    stage(2, 0);
    cp_wait<1>(); __syncthreads();
    compute(1);   __syncthreads();
    stage(3, 1);
    cp_wait<1>(); __syncthreads();
    compute(0);   __syncthreads();
    cp_wait<0>(); __syncthreads();
    compute(1);

    // ---- epilogue: exp + reductions -----------------------------------------
    float* rs = (float*)(sbp + SM_RS);
    float* cs = (float*)(sbp + SM_CS);
    if (tid < BM) { rs[tid] = 0.0f; cs[tid] = 0.0f; }
    __syncthreads();

    const float SC = 14.4269504088896340f;   // (1/temp) * log2(e)
    const int q = lane >> 2, p2 = (lane & 3) * 2;
    float* dd = g_d[z];
    const int grb = by * BM, gcb = bx * BN;

    float rp[8], cp_[8];
    #pragma unroll
    for (int i = 0; i < 8; i++) { rp[i] = 0.0f; cp_[i] = 0.0f; }

    #pragma unroll
    for (int mt = 0; mt < 4; mt++)
        #pragma unroll
        for (int nt = 0; nt < 4; nt++) {
            float e0 = ex2f(acc[mt][nt][0] * SC);
            float e1 = ex2f(acc[mt][nt][1] * SC);
            float e2 = ex2f(acc[mt][nt][2] * SC);
            float e3 = ex2f(acc[mt][nt][3] * SC);
            rp[mt * 2 + 0] += e0 + e1;
            rp[mt * 2 + 1] += e2 + e3;
            cp_[nt * 2 + 0] += e0 + e2;
            cp_[nt * 2 + 1] += e1 + e3;
            if (needDiag) {
                int r0 = rowT + mt * 16 + q, r1 = r0 + 8;
                int c0 = colT + nt * 8 + p2;
                if (r0 == c0)     dd[grb + r0] = e0;
                if (r0 == c0 + 1) dd[grb + r0] = e1;
                if (r1 == c0)     dd[grb + r1] = e2;
                if (r1 == c0 + 1) dd[grb + r1] = e3;
            }
        }

    // row sums: reduce over quad (lanes sharing t/4)
    #pragma unroll
    for (int o = 1; o <= 2; o <<= 1)
        #pragma unroll
        for (int i = 0; i < 8; i++) rp[i] += __shfl_xor_sync(0xffffffffu, rp[i], o);
    if ((lane & 3) == 0) {
        #pragma unroll
        for (int mt = 0; mt < 4; mt++) {
            atomicAdd(&rs[rowT + mt * 16 + q],     rp[mt * 2 + 0]);
            atomicAdd(&rs[rowT + mt * 16 + q + 8], rp[mt * 2 + 1]);
        }
    }
    // col sums: reduce over lanes sharing t%4
    if (needCol) {
        #pragma unroll
        for (int o = 4; o <= 16; o <<= 1)
            #pragma unroll
            for (int i = 0; i < 8; i++) cp_[i] += __shfl_xor_sync(0xffffffffu, cp_[i], o);
        if (lane < 4) {
            #pragma unroll
            for (int nt = 0; nt < 4; nt++) {
                atomicAdd(&cs[colT + nt * 8 + lane * 2],     cp_[nt * 2 + 0]);
                atomicAdd(&cs[colT + nt * 8 + lane * 2 + 1], cp_[nt * 2 + 1]);
            }
        }
    }
    __syncthreads();

    float* srow = g_s[z];
    if (tid < BM) {
        atomicAdd(&srow[grb + tid], rs[tid]);
        if (needCol) {
            float cv = cs[tid];
            int cloc = gcb + tid;
            if (z == 3)      atomicAdd(&g_c[0][cloc], cv);
            else if (z == 4) atomicAdd(&g_c[1][cloc], cv);
            else             atomicAdd(&srow[cloc], cv);  // symmetric fold
        }
    }
}

__global__ void loss_kernel(float* __restrict__ out) {
    __shared__ float red[256];
    float acc = 0.0f;
    for (int i = threadIdx.x; i < BSZ; i += blockDim.x) {
        float d0 = g_d[0][i], s0 = g_s[0][i];
        float d1 = g_d[1][i], s1 = g_s[1][i];
        float d2 = g_d[2][i], s2 = g_s[2][i];
        float d3 = g_d[3][i], s3 = g_s[3][i];
        float d4 = g_d[4][i], s4 = g_s[4][i];
        float c0 = g_c[0][i], c1 = g_c[1][i];
        float denom = (s2 - d2) + (s0 - d0) + (s1 - d1);
        float t = -2.0f * __logf(d2 / denom)
                  - __logf(d3 / (s3 - d3)) - __logf(d4 / (s4 - d4))
                  - __logf(d3 / (c0 - d3)) - __logf(d4 / (c1 - d4));
        acc += t;
    }
    red[threadIdx.x] = acc;
    __syncthreads();
    for (int s = 128; s; s >>= 1) {
        if (threadIdx.x < s) red[threadIdx.x] += red[threadIdx.x + s];
        __syncthreads();
    }
    if (threadIdx.x == 0) out[0] = red[0] * (1.0f / BSZ);
}

// ---------------------------------------------------------------------------
extern "C" void kernel_launch(void* const* d_in, const int* in_sizes, int n_in,
                              void* d_out, int out_size) {
    const float* x = (const float*)d_in[0];
    (void)in_sizes; (void)n_in; (void)out_size;

    cudaFuncSetAttribute(gemm_kernel, cudaFuncAttributeMaxDynamicSharedMemorySize,
                         SMEM_BYTES);

    zero_kernel<<<(5 * BSZ + 255) / 256, 256>>>();
    normalize_split_kernel<<<NROWS / 8, 256>>>(x);
    gemm_kernel<<<NBLK, 256, SMEM_BYTES>>>();
    loss_kernel<<<1, 256>>>((float*)d_out);
}

// round 4
// speedup vs baseline: 4.2206x; 1.0726x over previous
#include <cuda_runtime.h>
#include <cuda_bf16.h>
#include <cstdint>
#include <math.h>

#define NROWS 12288
#define DIM   128
#define BSZ   4096
#define KHL   256          // [hi|lo] concat-K (symmetric; lo*lo term is a bonus)
#define BM    128
#define BN    128
#define NT    32           // 4096 / 128
#define SYMT  528          // 32*33/2
#define NBLK  (2*SYMT + 3*NT*NT)   // 4128

// ---- device scratch --------------------------------------------------------
__device__ __align__(16) __nv_bfloat16 g_n[NROWS * KHL];  // [hi(128) | lo(128)]
__device__ float g_s[5][BSZ];   // row sums (xx, yy, xy, xz, yz)
__device__ float g_c[2][BSZ];   // col sums of xz, yz (== s_zx, s_zy)
__device__ float g_d[5][BSZ];   // diagonals

// ---- helpers ----------------------------------------------------------------
__device__ __forceinline__ uint32_t smem_u32(const void* p) {
    uint32_t a;
    asm("{ .reg .u64 t; cvta.to.shared.u64 t, %1; cvt.u32.u64 %0, t; }"
        : "=r"(a) : "l"(p));
    return a;
}
__device__ __forceinline__ float ex2f(float a) {
    float r; asm("ex2.approx.ftz.f32 %0, %1;" : "=f"(r) : "f"(a)); return r;
}
__device__ __forceinline__ void cp16(uint32_t dst, const void* src) {
    asm volatile("cp.async.cg.shared.global [%0], [%1], 16;"
                 :: "r"(dst), "l"(src) : "memory");
}
__device__ __forceinline__ void cp_commit() {
    asm volatile("cp.async.commit_group;" ::: "memory");
}
template <int N>
__device__ __forceinline__ void cp_wait() {
    asm volatile("cp.async.wait_group %0;" :: "n"(N) : "memory");
}
__device__ __forceinline__ void ldsm4(uint32_t* r, uint32_t a) {
    asm volatile("ldmatrix.sync.aligned.m8n8.x4.shared.b16 {%0,%1,%2,%3}, [%4];"
                 : "=r"(r[0]), "=r"(r[1]), "=r"(r[2]), "=r"(r[3]) : "r"(a));
}
__device__ __forceinline__ void mma16816(float* c, const uint32_t* a, const uint32_t* b) {
    asm volatile(
        "mma.sync.aligned.m16n8k16.row.col.f32.bf16.bf16.f32 "
        "{%0,%1,%2,%3}, {%4,%5,%6,%7}, {%8,%9}, {%0,%1,%2,%3};"
        : "+f"(c[0]), "+f"(c[1]), "+f"(c[2]), "+f"(c[3])
        : "r"(a[0]), "r"(a[1]), "r"(a[2]), "r"(a[3]), "r"(b[0]), "r"(b[1]));
}

// ---- normalize + split + zero scratch ---------------------------------------
__global__ void normalize_split_kernel(const float* __restrict__ x) {
    // fold scratch zeroing into this kernel (saves a launch)
    int zi = blockIdx.x * 256 + threadIdx.x;
    if (zi < 5 * BSZ)                      ((float*)g_s)[zi] = 0.0f;
    else if (zi < 5 * BSZ + 2 * BSZ)       ((float*)g_c)[zi - 5 * BSZ] = 0.0f;

    int row  = blockIdx.x * 8 + (threadIdx.x >> 5);
    int lane = threadIdx.x & 31;
    float4 v = ((const float4*)(x + (size_t)row * DIM))[lane];
    float ss = fmaf(v.x, v.x, fmaf(v.y, v.y, fmaf(v.z, v.z, v.w * v.w)));
    #pragma unroll
    for (int o = 16; o; o >>= 1) ss += __shfl_xor_sync(0xffffffffu, ss, o);
    float inv = rsqrtf(fmaxf(ss, 1e-24f));
    float xv[4] = {v.x * inv, v.y * inv, v.z * inv, v.w * inv};

    __nv_bfloat16 hi[4], lo[4];
    #pragma unroll
    for (int c = 0; c < 4; c++) {
        hi[c] = __float2bfloat16(xv[c]);
        lo[c] = __float2bfloat16(xv[c] - __bfloat162float(hi[c]));
    }
    __nv_bfloat162 h01(hi[0], hi[1]), h23(hi[2], hi[3]);
    __nv_bfloat162 l01(lo[0], lo[1]), l23(lo[2], lo[3]);
    size_t base = (size_t)row * KHL + lane * 4;
    *(uint2*)(g_n + base)       = make_uint2(*(uint32_t*)&h01, *(uint32_t*)&h23);
    *(uint2*)(g_n + base + 128) = make_uint2(*(uint32_t*)&l01, *(uint32_t*)&l23);
}

// ---- main GEMM + fused exp/reduce ------------------------------------------
// dyn smem: 3 stages x (A 16K | B 16K) | rs 512 | cs 512
#define SM_A(b)   ((b) * 32768)
#define SM_B(b)   ((b) * 32768 + 16384)
#define SM_RS     98304
#define SM_CS     (98304 + 512)
#define SMEM_BYTES (98304 + 1024)

__global__ void __launch_bounds__(256, 2) gemm_kernel() {
    extern __shared__ char sbp[];
    const uint32_t sb = smem_u32(sbp);

    const int tid = threadIdx.x, wid = tid >> 5, lane = tid & 31;

    // block -> (z, by, bx)
    int idx = blockIdx.x;
    int z, by, bx;
    if (idx < 2 * SYMT) {
        z = idx < SYMT ? 0 : 1;
        int t = idx - z * SYMT, r = 0;
        while (t >= NT - r) { t -= NT - r; r++; }
        by = r; bx = r + t;                       // upper triangle incl diag
    } else {
        int t = idx - 2 * SYMT;
        z = 2 + t / (NT * NT); t %= NT * NT;
        by = t / NT; bx = t % NT;
    }
    const int aoffs[5] = {0, 1, 0, 0, 1};
    const int boffs[5] = {0, 1, 1, 2, 2};
    const bool sym      = (z < 2);
    const bool needCol  = (z >= 3) || (sym && bx > by);
    const bool needDiag = (by == bx);

    const char* Agp = (const char*)g_n + (size_t)(aoffs[z] * BSZ + by * BM) * (KHL * 2);
    const char* Bgp = (const char*)g_n + (size_t)(boffs[z] * BSZ + bx * BN) * (KHL * 2);

    // ---- staging: 128 rows x 64 bf16 (128B) per matrix per stage -----------
    const int lrow = tid >> 3, lseg = tid & 7;          // covers 32 rows/iter
    auto stage = [&](int s, int b) {
        #pragma unroll
        for (int it = 0; it < 4; it++) {
            int row = lrow + it * 32;
            uint32_t off = (uint32_t)(row * 128 + lseg * 16);
            uint32_t sw  = off ^ ((row & 7) << 4);
            size_t go = (size_t)row * 512 + s * 128 + lseg * 16;
            cp16(sb + SM_A(b) + sw, Agp + go);
            cp16(sb + SM_B(b) + sw, Bgp + go);
        }
        cp_commit();
    };

    const int warp_m = wid >> 2, warp_n = wid & 3;      // 2 x 4 warp grid
    const int rowT = warp_m * 64, colT = warp_n * 32;
    const int lr16 = lane & 15, lcs = (lane >> 4) * 16; // ldmatrix addressing

    float acc[4][4][4];
    #pragma unroll
    for (int i = 0; i < 4; i++)
        #pragma unroll
        for (int j = 0; j < 4; j++)
            #pragma unroll
            for (int e = 0; e < 4; e++) acc[i][j][e] = 0.0f;

    auto compute = [&](int b) {
        #pragma unroll
        for (int k16 = 0; k16 < 4; k16++) {
            uint32_t af[4][4], bf[2][4];
            #pragma unroll
            for (int mt = 0; mt < 4; mt++) {
                int row = rowT + mt * 16 + lr16;
                uint32_t off = (uint32_t)(row * 128 + k16 * 32 + lcs);
                ldsm4(af[mt], sb + SM_A(b) + (off ^ ((row & 7) << 4)));
            }
            #pragma unroll
            for (int nb = 0; nb < 2; nb++) {
                int row = colT + nb * 16 + lr16;
                uint32_t off = (uint32_t)(row * 128 + k16 * 32 + lcs);
                ldsm4(bf[nb], sb + SM_B(b) + (off ^ ((row & 7) << 4)));
            }
            #pragma unroll
            for (int mt = 0; mt < 4; mt++)
                #pragma unroll
                for (int nt = 0; nt < 4; nt++) {
                    uint32_t bb[2] = {bf[nt >> 1][nt & 1], bf[nt >> 1][(nt & 1) + 2]};
                    mma16816(acc[mt][nt], af[mt], bb);
                }
        }
    };

    // ---- 3-buffer pipelined mainloop over 4 K-chunks (5 barriers) ----------
    stage(0, 0);
    stage(1, 1);
    stage(2, 2);
    cp_wait<2>(); __syncthreads();
    compute(0);
    __syncthreads();           // all warps done reading buf0
    stage(3, 0);
    cp_wait<2>(); __syncthreads();
    compute(1);
    cp_wait<1>(); __syncthreads();
    compute(2);
    cp_wait<0>(); __syncthreads();
    compute(0);

    // ---- epilogue: exp + reductions -----------------------------------------
    float* rs = (float*)(sbp + SM_RS);
    float* cs = (float*)(sbp + SM_CS);
    if (tid < BM) { rs[tid] = 0.0f; cs[tid] = 0.0f; }
    __syncthreads();

    const float SC = 14.4269504088896340f;   // (1/temp) * log2(e)
    const int q = lane >> 2, p2 = (lane & 3) * 2;
    float* dd = g_d[z];
    const int grb = by * BM, gcb = bx * BN;

    float rp[8], cp_[8];
    #pragma unroll
    for (int i = 0; i < 8; i++) { rp[i] = 0.0f; cp_[i] = 0.0f; }

    #pragma unroll
    for (int mt = 0; mt < 4; mt++)
        #pragma unroll
        for (int nt = 0; nt < 4; nt++) {
            float e0 = ex2f(acc[mt][nt][0] * SC);
            float e1 = ex2f(acc[mt][nt][1] * SC);
            float e2 = ex2f(acc[mt][nt][2] * SC);
            float e3 = ex2f(acc[mt][nt][3] * SC);
            rp[mt * 2 + 0] += e0 + e1;
            rp[mt * 2 + 1] += e2 + e3;
            cp_[nt * 2 + 0] += e0 + e2;
            cp_[nt * 2 + 1] += e1 + e3;
            if (needDiag) {
                int r0 = rowT + mt * 16 + q, r1 = r0 + 8;
                int c0 = colT + nt * 8 + p2;
                if (r0 == c0)     dd[grb + r0] = e0;
                if (r0 == c0 + 1) dd[grb + r0] = e1;
                if (r1 == c0)     dd[grb + r1] = e2;
                if (r1 == c0 + 1) dd[grb + r1] = e3;
            }
        }

    // row sums: reduce over quad (lanes sharing t/4)
    #pragma unroll
    for (int o = 1; o <= 2; o <<= 1)
        #pragma unroll
        for (int i = 0; i < 8; i++) rp[i] += __shfl_xor_sync(0xffffffffu, rp[i], o);
    if ((lane & 3) == 0) {
        #pragma unroll
        for (int mt = 0; mt < 4; mt++) {
            atomicAdd(&rs[rowT + mt * 16 + q],     rp[mt * 2 + 0]);
            atomicAdd(&rs[rowT + mt * 16 + q + 8], rp[mt * 2 + 1]);
        }
    }
    // col sums: reduce over lanes sharing t%4
    if (needCol) {
        #pragma unroll
        for (int o = 4; o <= 16; o <<= 1)
            #pragma unroll
            for (int i = 0; i < 8; i++) cp_[i] += __shfl_xor_sync(0xffffffffu, cp_[i], o);
        if (lane < 4) {
            #pragma unroll
            for (int nt = 0; nt < 4; nt++) {
                atomicAdd(&cs[colT + nt * 8 + lane * 2],     cp_[nt * 2 + 0]);
                atomicAdd(&cs[colT + nt * 8 + lane * 2 + 1], cp_[nt * 2 + 1]);
            }
        }
    }
    __syncthreads();

    float* srow = g_s[z];
    if (tid < BM) {
        atomicAdd(&srow[grb + tid], rs[tid]);
        if (needCol) {
            float cv = cs[tid];
            int cloc = gcb + tid;
            if (z == 3)      atomicAdd(&g_c[0][cloc], cv);
            else if (z == 4) atomicAdd(&g_c[1][cloc], cv);
            else             atomicAdd(&srow[cloc], cv);  // symmetric fold
        }
    }
}

// ---- final loss: 1024 threads, 4 rows each, latency-overlapped --------------
__global__ void __launch_bounds__(1024) loss_kernel(float* __restrict__ out) {
    __shared__ float red[1024];
    float acc = 0.0f;
    #pragma unroll
    for (int it = 0; it < 4; it++) {
        int i = threadIdx.x + it * 1024;
        float d0 = g_d[0][i], s0 = g_s[0][i];
        float d1 = g_d[1][i], s1 = g_s[1][i];
        float d2 = g_d[2][i], s2 = g_s[2][i];
        float d3 = g_d[3][i], s3 = g_s[3][i];
        float d4 = g_d[4][i], s4 = g_s[4][i];
        float c0 = g_c[0][i], c1 = g_c[1][i];
        float denom = (s2 - d2) + (s0 - d0) + (s1 - d1);
        acc += -2.0f * __logf(d2 / denom)
               - __logf(d3 / (s3 - d3)) - __logf(d4 / (s4 - d4))
               - __logf(d3 / (c0 - d3)) - __logf(d4 / (c1 - d4));
    }
    red[threadIdx.x] = acc;
    __syncthreads();
    for (int s = 512; s >= 32; s >>= 1) {
        if (threadIdx.x < s) red[threadIdx.x] += red[threadIdx.x + s];
        __syncthreads();
    }
    if (threadIdx.x < 32) {
        float v = red[threadIdx.x];
        #pragma unroll
        for (int o = 16; o; o >>= 1) v += __shfl_xor_sync(0xffffffffu, v, o);
        if (threadIdx.x == 0) out[0] = v * (1.0f / BSZ);
    }
}

// ---------------------------------------------------------------------------
extern "C" void kernel_launch(void* const* d_in, const int* in_sizes, int n_in,
                              void* d_out, int out_size) {
    const float* x = (const float*)d_in[0];
    (void)in_sizes; (void)n_in; (void)out_size;

    cudaFuncSetAttribute(gemm_kernel, cudaFuncAttributeMaxDynamicSharedMemorySize,
                         SMEM_BYTES);

    normalize_split_kernel<<<NROWS / 8, 256>>>(x);
    gemm_kernel<<<NBLK, 256, SMEM_BYTES>>>();
    loss_kernel<<<1, 1024>>>((float*)d_out);
}

// round 5
// speedup vs baseline: 6.4968x; 1.5393x over previous
#include <cuda_runtime.h>
#include <cuda_bf16.h>
#include <cstdint>
#include <math.h>

#define NROWS 12288
#define DIM   128
#define BSZ   4096
#define BM    128
#define BN    128
#define NT    32           // 4096 / 128
#define SYMT  528          // 32*33/2
#define NBLK  (2*SYMT + 3*NT*NT)   // 4128

// ---- device scratch --------------------------------------------------------
__device__ __align__(16) __nv_bfloat16 g_n[NROWS * DIM];  // normalized bf16
__device__ float g_s[5][BSZ];   // row sums (xx, yy, xy, xz, yz)
__device__ float g_c[2][BSZ];   // col sums of xz, yz (== s_zx, s_zy)
__device__ float g_d[5][BSZ];   // diagonals

// ---- helpers ----------------------------------------------------------------
__device__ __forceinline__ uint32_t smem_u32(const void* p) {
    uint32_t a;
    asm("{ .reg .u64 t; cvta.to.shared.u64 t, %1; cvt.u32.u64 %0, t; }"
        : "=r"(a) : "l"(p));
    return a;
}
__device__ __forceinline__ float ex2f(float a) {
    float r; asm("ex2.approx.ftz.f32 %0, %1;" : "=f"(r) : "f"(a)); return r;
}
__device__ __forceinline__ void cp16(uint32_t dst, const void* src) {
    asm volatile("cp.async.cg.shared.global [%0], [%1], 16;"
                 :: "r"(dst), "l"(src) : "memory");
}
__device__ __forceinline__ void cp_commit() {
    asm volatile("cp.async.commit_group;" ::: "memory");
}
template <int N>
__device__ __forceinline__ void cp_wait() {
    asm volatile("cp.async.wait_group %0;" :: "n"(N) : "memory");
}
__device__ __forceinline__ void ldsm4(uint32_t* r, uint32_t a) {
    asm volatile("ldmatrix.sync.aligned.m8n8.x4.shared.b16 {%0,%1,%2,%3}, [%4];"
                 : "=r"(r[0]), "=r"(r[1]), "=r"(r[2]), "=r"(r[3]) : "r"(a));
}
__device__ __forceinline__ void mma16816(float* c, const uint32_t* a, const uint32_t* b) {
    asm volatile(
        "mma.sync.aligned.m16n8k16.row.col.f32.bf16.bf16.f32 "
        "{%0,%1,%2,%3}, {%4,%5,%6,%7}, {%8,%9}, {%0,%1,%2,%3};"
        : "+f"(c[0]), "+f"(c[1]), "+f"(c[2]), "+f"(c[3])
        : "r"(a[0]), "r"(a[1]), "r"(a[2]), "r"(a[3]), "r"(b[0]), "r"(b[1]));
}

// ---- normalize (+ zero scratch, fused) --------------------------------------
__global__ void normalize_kernel(const float* __restrict__ x) {
    int zi = blockIdx.x * 256 + threadIdx.x;
    if (zi < 5 * BSZ)                ((float*)g_s)[zi] = 0.0f;
    else if (zi < 7 * BSZ)           ((float*)g_c)[zi - 5 * BSZ] = 0.0f;

    int row  = blockIdx.x * 8 + (threadIdx.x >> 5);
    int lane = threadIdx.x & 31;
    float4 v = ((const float4*)(x + (size_t)row * DIM))[lane];
    float ss = fmaf(v.x, v.x, fmaf(v.y, v.y, fmaf(v.z, v.z, v.w * v.w)));
    #pragma unroll
    for (int o = 16; o; o >>= 1) ss += __shfl_xor_sync(0xffffffffu, ss, o);
    float inv = rsqrtf(fmaxf(ss, 1e-24f));

    __nv_bfloat162 h01(__float2bfloat16(v.x * inv), __float2bfloat16(v.y * inv));
    __nv_bfloat162 h23(__float2bfloat16(v.z * inv), __float2bfloat16(v.w * inv));
    *(uint2*)(g_n + (size_t)row * DIM + lane * 4) =
        make_uint2(*(uint32_t*)&h01, *(uint32_t*)&h23);
}

// ---- main GEMM + fused exp/reduce ------------------------------------------
// dyn smem: A 32K | B 32K | rs 512 | cs 512   (whole K=128 resident)
#define SM_A      0
#define SM_B      32768
#define SM_RS     65536
#define SM_CS     (65536 + 512)
#define SMEM_BYTES (65536 + 1024)

__global__ void __launch_bounds__(256, 2) gemm_kernel() {
    extern __shared__ char sbp[];
    const uint32_t sb = smem_u32(sbp);

    const int tid = threadIdx.x, wid = tid >> 5, lane = tid & 31;

    // block -> (z, by, bx)
    int idx = blockIdx.x;
    int z, by, bx;
    if (idx < 2 * SYMT) {
        z = idx < SYMT ? 0 : 1;
        int t = idx - z * SYMT, r = 0;
        while (t >= NT - r) { t -= NT - r; r++; }
        by = r; bx = r + t;                       // upper triangle incl diag
    } else {
        int t = idx - 2 * SYMT;
        z = 2 + t / (NT * NT); t %= NT * NT;
        by = t / NT; bx = t % NT;
    }
    const int aoffs[5] = {0, 1, 0, 0, 1};
    const int boffs[5] = {0, 1, 1, 2, 2};
    const bool sym      = (z < 2);
    const bool needCol  = (z >= 3) || (sym && bx > by);
    const bool needDiag = (by == bx);

    const char* Agp = (const char*)g_n + (size_t)(aoffs[z] * BSZ + by * BM) * (DIM * 2);
    const char* Bgp = (const char*)g_n + (size_t)(boffs[z] * BSZ + bx * BN) * (DIM * 2);

    // ---- stage: rows are 256B; swizzle XOR (row&7)<<4 for ldmatrix ---------
    auto stage = [&](int half) {   // half = byte range [half*128, half*128+128)
        int rowQ = tid >> 3, seg = tid & 7;      // 32 rows per iter
        #pragma unroll
        for (int it = 0; it < 4; it++) {
            int row = rowQ + it * 32;
            uint32_t off = (uint32_t)(row * 256 + half * 128 + seg * 16);
            uint32_t sw  = off ^ ((row & 7) << 4);
            cp16(sb + SM_A + sw, Agp + off);
            cp16(sb + SM_B + sw, Bgp + off);
        }
        cp_commit();
    };

    const int warp_m = wid >> 2, warp_n = wid & 3;      // 2 x 4 warp grid
    const int rowT = warp_m * 64, colT = warp_n * 32;
    const int lr16 = lane & 15, lcs = (lane >> 4) * 16;

    float acc[4][4][4];
    #pragma unroll
    for (int i = 0; i < 4; i++)
        #pragma unroll
        for (int j = 0; j < 4; j++)
            #pragma unroll
            for (int e = 0; e < 4; e++) acc[i][j][e] = 0.0f;

    auto compute = [&](int k16lo, int k16hi) {
        #pragma unroll
        for (int k16 = k16lo; k16 < k16hi; k16++) {
            uint32_t af[4][4], bf[2][4];
            #pragma unroll
            for (int mt = 0; mt < 4; mt++) {
                int row = rowT + mt * 16 + lr16;
                uint32_t off = (uint32_t)(row * 256 + k16 * 32 + lcs);
                ldsm4(af[mt], sb + SM_A + (off ^ ((row & 7) << 4)));
            }
            #pragma unroll
            for (int nb = 0; nb < 2; nb++) {
                int row = colT + nb * 16 + lr16;
                uint32_t off = (uint32_t)(row * 256 + k16 * 32 + lcs);
                ldsm4(bf[nb], sb + SM_B + (off ^ ((row & 7) << 4)));
            }
            #pragma unroll
            for (int mt = 0; mt < 4; mt++)
                #pragma unroll
                for (int nt = 0; nt < 4; nt++) {
                    uint32_t bb[2] = {bf[nt >> 1][nt & 1], bf[nt >> 1][(nt & 1) + 2]};
                    mma16816(acc[mt][nt], af[mt], bb);
                }
        }
    };

    // ---- mainloop: two K-halves, minimal barriers ---------------------------
    stage(0);
    stage(1);
    cp_wait<1>(); __syncthreads();
    compute(0, 4);
    cp_wait<0>(); __syncthreads();
    compute(4, 8);

    // ---- epilogue: exp + reductions -----------------------------------------
    float* rs = (float*)(sbp + SM_RS);
    float* cs = (float*)(sbp + SM_CS);
    __syncthreads();                 // smem tiles no longer needed
    if (tid < BM) { rs[tid] = 0.0f; cs[tid] = 0.0f; }
    __syncthreads();

    const float SC = 14.4269504088896340f;   // (1/temp) * log2(e)
    const int q = lane >> 2, p2 = (lane & 3) * 2;
    float* dd = g_d[z];
    const int grb = by * BM, gcb = bx * BN;

    float rp[8], cp_[8];
    #pragma unroll
    for (int i = 0; i < 8; i++) { rp[i] = 0.0f; cp_[i] = 0.0f; }

    #pragma unroll
    for (int mt = 0; mt < 4; mt++)
        #pragma unroll
        for (int nt = 0; nt < 4; nt++) {
            float e0 = ex2f(acc[mt][nt][0] * SC);
            float e1 = ex2f(acc[mt][nt][1] * SC);
            float e2 = ex2f(acc[mt][nt][2] * SC);
            float e3 = ex2f(acc[mt][nt][3] * SC);
            rp[mt * 2 + 0] += e0 + e1;
            rp[mt * 2 + 1] += e2 + e3;
            cp_[nt * 2 + 0] += e0 + e2;
            cp_[nt * 2 + 1] += e1 + e3;
            if (needDiag) {
                int r0 = rowT + mt * 16 + q, r1 = r0 + 8;
                int c0 = colT + nt * 8 + p2;
                if (r0 == c0)     dd[grb + r0] = e0;
                if (r0 == c0 + 1) dd[grb + r0] = e1;
                if (r1 == c0)     dd[grb + r1] = e2;
                if (r1 == c0 + 1) dd[grb + r1] = e3;
            }
        }

    // row sums: reduce over quad (lanes sharing t/4)
    #pragma unroll
    for (int o = 1; o <= 2; o <<= 1)
        #pragma unroll
        for (int i = 0; i < 8; i++) rp[i] += __shfl_xor_sync(0xffffffffu, rp[i], o);
    if ((lane & 3) == 0) {
        #pragma unroll
        for (int mt = 0; mt < 4; mt++) {
            atomicAdd(&rs[rowT + mt * 16 + q],     rp[mt * 2 + 0]);
            atomicAdd(&rs[rowT + mt * 16 + q + 8], rp[mt * 2 + 1]);
        }
    }
    // col sums: reduce over lanes sharing t%4
    if (needCol) {
        #pragma unroll
        for (int o = 4; o <= 16; o <<= 1)
            #pragma unroll
            for (int i = 0; i < 8; i++) cp_[i] += __shfl_xor_sync(0xffffffffu, cp_[i], o);
        if (lane < 4) {
            #pragma unroll
            for (int nt = 0; nt < 4; nt++) {
                atomicAdd(&cs[colT + nt * 8 + lane * 2],     cp_[nt * 2 + 0]);
                atomicAdd(&cs[colT + nt * 8 + lane * 2 + 1], cp_[nt * 2 + 1]);
            }
        }
    }
    __syncthreads();

    float* srow = g_s[z];
    if (tid < BM) {
        atomicAdd(&srow[grb + tid], rs[tid]);
        if (needCol) {
            float cv = cs[tid];
            int cloc = gcb + tid;
            if (z == 3)      atomicAdd(&g_c[0][cloc], cv);
            else if (z == 4) atomicAdd(&g_c[1][cloc], cv);
            else             atomicAdd(&srow[cloc], cv);  // symmetric fold
        }
    }
}

// ---- final loss: 1024 threads, 4 rows each ----------------------------------
__global__ void __launch_bounds__(1024) loss_kernel(float* __restrict__ out) {
    __shared__ float red[1024];
    float acc = 0.0f;
    #pragma unroll
    for (int it = 0; it < 4; it++) {
        int i = threadIdx.x + it * 1024;
        float d0 = g_d[0][i], s0 = g_s[0][i];
        float d1 = g_d[1][i], s1 = g_s[1][i];
        float d2 = g_d[2][i], s2 = g_s[2][i];
        float d3 = g_d[3][i], s3 = g_s[3][i];
        float d4 = g_d[4][i], s4 = g_s[4][i];
        float c0 = g_c[0][i], c1 = g_c[1][i];
        float denom = (s2 - d2) + (s0 - d0) + (s1 - d1);
        acc += -2.0f * __logf(d2 / denom)
               - __logf(d3 / (s3 - d3)) - __logf(d4 / (s4 - d4))
               - __logf(d3 / (c0 - d3)) - __logf(d4 / (c1 - d4));
    }
    red[threadIdx.x] = acc;
    __syncthreads();
    for (int s = 512; s >= 32; s >>= 1) {
        if (threadIdx.x < s) red[threadIdx.x] += red[threadIdx.x + s];
        __syncthreads();
    }
    if (threadIdx.x < 32) {
        float v = red[threadIdx.x];
        #pragma unroll
        for (int o = 16; o; o >>= 1) v += __shfl_xor_sync(0xffffffffu, v, o);
        if (threadIdx.x == 0) out[0] = v * (1.0f / BSZ);
    }
}

// ---------------------------------------------------------------------------
extern "C" void kernel_launch(void* const* d_in, const int* in_sizes, int n_in,
                              void* d_out, int out_size) {
    const float* x = (const float*)d_in[0];
    (void)in_sizes; (void)n_in; (void)out_size;

    cudaFuncSetAttribute(gemm_kernel, cudaFuncAttributeMaxDynamicSharedMemorySize,
                         SMEM_BYTES);

    normalize_kernel<<<NROWS / 8, 256>>>(x);
    gemm_kernel<<<NBLK, 256, SMEM_BYTES>>>();
    loss_kernel<<<1, 1024>>>((float*)d_out);
}

// round 6
// speedup vs baseline: 7.4920x; 1.1532x over previous
#include <cuda_runtime.h>
#include <cuda_fp16.h>
#include <cstdint>
#include <math.h>

#define NROWS 12288
#define DIM   128
#define BSZ   4096
#define BM    128
#define BN    128
#define NT    32           // 4096 / 128
#define SYMT  528          // 32*33/2
#define NBLK  (2*SYMT + 3*NT*NT)   // 4128

// ---- device scratch --------------------------------------------------------
__device__ __align__(16) __half g_n[NROWS * DIM];  // normalized fp16
__device__ float g_s[5][BSZ];   // row sums (xx, yy, xy, xz, yz)
__device__ float g_c[2][BSZ];   // col sums of xz, yz (== s_zx, s_zy)
__device__ float g_d[5][BSZ];   // diagonals

// ---- helpers ----------------------------------------------------------------
__device__ __forceinline__ uint32_t smem_u32(const void* p) {
    uint32_t a;
    asm("{ .reg .u64 t; cvta.to.shared.u64 t, %1; cvt.u32.u64 %0, t; }"
        : "=r"(a) : "l"(p));
    return a;
}
__device__ __forceinline__ float ex2f(float a) {
    float r; asm("ex2.approx.ftz.f32 %0, %1;" : "=f"(r) : "f"(a)); return r;
}
__device__ __forceinline__ void cp16(uint32_t dst, const void* src) {
    asm volatile("cp.async.cg.shared.global [%0], [%1], 16;"
                 :: "r"(dst), "l"(src) : "memory");
}
__device__ __forceinline__ void cp_commit() {
    asm volatile("cp.async.commit_group;" ::: "memory");
}
template <int N>
__device__ __forceinline__ void cp_wait() {
    asm volatile("cp.async.wait_group %0;" :: "n"(N) : "memory");
}
__device__ __forceinline__ void ldsm4(uint32_t* r, uint32_t a) {
    asm volatile("ldmatrix.sync.aligned.m8n8.x4.shared.b16 {%0,%1,%2,%3}, [%4];"
                 : "=r"(r[0]), "=r"(r[1]), "=r"(r[2]), "=r"(r[3]) : "r"(a));
}
// fp16-in, fp16-accumulate MMA (packed f16x2 C)
__device__ __forceinline__ void mma16816h(uint32_t* c, const uint32_t* a, const uint32_t* b) {
    asm volatile(
        "mma.sync.aligned.m16n8k16.row.col.f16.f16.f16.f16 "
        "{%0,%1}, {%2,%3,%4,%5}, {%6,%7}, {%0,%1};"
        : "+r"(c[0]), "+r"(c[1])
        : "r"(a[0]), "r"(a[1]), "r"(a[2]), "r"(a[3]), "r"(b[0]), "r"(b[1]));
}

// ---- normalize (+ zero scratch, fused) --------------------------------------
__global__ void normalize_kernel(const float* __restrict__ x) {
    int zi = blockIdx.x * 256 + threadIdx.x;
    if (zi < 5 * BSZ)                ((float*)g_s)[zi] = 0.0f;
    else if (zi < 7 * BSZ)           ((float*)g_c)[zi - 5 * BSZ] = 0.0f;

    int row  = blockIdx.x * 8 + (threadIdx.x >> 5);
    int lane = threadIdx.x & 31;
    float4 v = ((const float4*)(x + (size_t)row * DIM))[lane];
    float ss = fmaf(v.x, v.x, fmaf(v.y, v.y, fmaf(v.z, v.z, v.w * v.w)));
    #pragma unroll
    for (int o = 16; o; o >>= 1) ss += __shfl_xor_sync(0xffffffffu, ss, o);
    float inv = rsqrtf(fmaxf(ss, 1e-24f));

    __half2 h01 = __floats2half2_rn(v.x * inv, v.y * inv);
    __half2 h23 = __floats2half2_rn(v.z * inv, v.w * inv);
    *(uint2*)(g_n + (size_t)row * DIM + lane * 4) =
        make_uint2(*(uint32_t*)&h01, *(uint32_t*)&h23);
}

// ---- main GEMM + fused exp/reduce ------------------------------------------
// dyn smem: A 32K | B 32K | rs 512 | cs 512   (whole K=128 resident)
#define SM_A      0
#define SM_B      32768
#define SM_RS     65536
#define SM_CS     (65536 + 512)
#define SMEM_BYTES (65536 + 1024)

__global__ void __launch_bounds__(256, 2) gemm_kernel() {
    extern __shared__ char sbp[];
    const uint32_t sb = smem_u32(sbp);

    const int tid = threadIdx.x, wid = tid >> 5, lane = tid & 31;

    // block -> (z, by, bx)
    int idx = blockIdx.x;
    int z, by, bx;
    if (idx < 2 * SYMT) {
        z = idx < SYMT ? 0 : 1;
        int t = idx - z * SYMT, r = 0;
        while (t >= NT - r) { t -= NT - r; r++; }
        by = r; bx = r + t;                       // upper triangle incl diag
    } else {
        int t = idx - 2 * SYMT;
        z = 2 + t / (NT * NT); t %= NT * NT;
        by = t / NT; bx = t % NT;
    }
    const int aoffs[5] = {0, 1, 0, 0, 1};
    const int boffs[5] = {0, 1, 1, 2, 2};
    const bool sym      = (z < 2);
    const bool needCol  = (z >= 3) || (sym && bx > by);
    const bool needDiag = (by == bx);

    const char* Agp = (const char*)g_n + (size_t)(aoffs[z] * BSZ + by * BM) * (DIM * 2);
    const char* Bgp = (const char*)g_n + (size_t)(boffs[z] * BSZ + bx * BN) * (DIM * 2);

    // ---- stage: rows are 256B; swizzle XOR (row&7)<<4 for ldmatrix ---------
    auto stage = [&](int half) {
        int rowQ = tid >> 3, seg = tid & 7;
        #pragma unroll
        for (int it = 0; it < 4; it++) {
            int row = rowQ + it * 32;
            uint32_t off = (uint32_t)(row * 256 + half * 128 + seg * 16);
            uint32_t sw  = off ^ ((row & 7) << 4);
            cp16(sb + SM_A + sw, Agp + off);
            cp16(sb + SM_B + sw, Bgp + off);
        }
        cp_commit();
    };

    const int warp_m = wid >> 2, warp_n = wid & 3;      // 2 x 4 warp grid
    const int rowT = warp_m * 64, colT = warp_n * 32;
    const int lr16 = lane & 15, lcs = (lane >> 4) * 16;

    uint32_t acc[4][4][2];   // packed f16x2: [0]={c0,c1} rows q, [1]={c2,c3} rows q+8
    #pragma unroll
    for (int i = 0; i < 4; i++)
        #pragma unroll
        for (int j = 0; j < 4; j++) { acc[i][j][0] = 0u; acc[i][j][1] = 0u; }

    auto compute = [&](int k16lo, int k16hi) {
        #pragma unroll
        for (int k16 = k16lo; k16 < k16hi; k16++) {
            uint32_t af[4][4], bf[2][4];
            #pragma unroll
            for (int mt = 0; mt < 4; mt++) {
                int row = rowT + mt * 16 + lr16;
                uint32_t off = (uint32_t)(row * 256 + k16 * 32 + lcs);
                ldsm4(af[mt], sb + SM_A + (off ^ ((row & 7) << 4)));
            }
            #pragma unroll
            for (int nb = 0; nb < 2; nb++) {
                int row = colT + nb * 16 + lr16;
                uint32_t off = (uint32_t)(row * 256 + k16 * 32 + lcs);
                ldsm4(bf[nb], sb + SM_B + (off ^ ((row & 7) << 4)));
            }
            #pragma unroll
            for (int mt = 0; mt < 4; mt++)
                #pragma unroll
                for (int nt = 0; nt < 4; nt++) {
                    uint32_t bb[2] = {bf[nt >> 1][nt & 1], bf[nt >> 1][(nt & 1) + 2]};
                    mma16816h(acc[mt][nt], af[mt], bb);
                }
        }
    };

    // ---- mainloop: two K-halves, minimal barriers ---------------------------
    stage(0);
    stage(1);
    cp_wait<1>(); __syncthreads();
    compute(0, 4);
    cp_wait<0>(); __syncthreads();
    compute(4, 8);

    // ---- epilogue: exp + reductions -----------------------------------------
    float* rs = (float*)(sbp + SM_RS);
    float* cs = (float*)(sbp + SM_CS);
    __syncthreads();
    if (tid < BM) { rs[tid] = 0.0f; cs[tid] = 0.0f; }
    __syncthreads();

    const float SC = 14.4269504088896340f;   // (1/temp) * log2(e)
    const int q = lane >> 2, p2 = (lane & 3) * 2;
    float* dd = g_d[z];
    const int grb = by * BM, gcb = bx * BN;

    float rp[8], cp_[8];
    #pragma unroll
    for (int i = 0; i < 8; i++) { rp[i] = 0.0f; cp_[i] = 0.0f; }

    #pragma unroll
    for (int mt = 0; mt < 4; mt++)
        #pragma unroll
        for (int nt = 0; nt < 4; nt++) {
            __half2 h0 = *(__half2*)&acc[mt][nt][0];
            __half2 h1 = *(__half2*)&acc[mt][nt][1];
            float e0 = ex2f(__half2float(h0.x) * SC);
            float e1 = ex2f(__half2float(h0.y) * SC);
            float e2 = ex2f(__half2float(h1.x) * SC);
            float e3 = ex2f(__half2float(h1.y) * SC);
            rp[mt * 2 + 0] += e0 + e1;
            rp[mt * 2 + 1] += e2 + e3;
            cp_[nt * 2 + 0] += e0 + e2;
            cp_[nt * 2 + 1] += e1 + e3;
            if (needDiag) {
                int r0 = rowT + mt * 16 + q, r1 = r0 + 8;
                int c0 = colT + nt * 8 + p2;
                if (r0 == c0)     dd[grb + r0] = e0;
                if (r0 == c0 + 1) dd[grb + r0] = e1;
                if (r1 == c0)     dd[grb + r1] = e2;
                if (r1 == c0 + 1) dd[grb + r1] = e3;
            }
        }

    // row sums: reduce over quad (lanes sharing t/4)
    #pragma unroll
    for (int o = 1; o <= 2; o <<= 1)
        #pragma unroll
        for (int i = 0; i < 8; i++) rp[i] += __shfl_xor_sync(0xffffffffu, rp[i], o);
    if ((lane & 3) == 0) {
        #pragma unroll
        for (int mt = 0; mt < 4; mt++) {
            atomicAdd(&rs[rowT + mt * 16 + q],     rp[mt * 2 + 0]);
            atomicAdd(&rs[rowT + mt * 16 + q + 8], rp[mt * 2 + 1]);
        }
    }
    // col sums: reduce over lanes sharing t%4
    if (needCol) {
        #pragma unroll
        for (int o = 4; o <= 16; o <<= 1)
            #pragma unroll
            for (int i = 0; i < 8; i++) cp_[i] += __shfl_xor_sync(0xffffffffu, cp_[i], o);
        if (lane < 4) {
            #pragma unroll
            for (int nt = 0; nt < 4; nt++) {
                atomicAdd(&cs[colT + nt * 8 + lane * 2],     cp_[nt * 2 + 0]);
                atomicAdd(&cs[colT + nt * 8 + lane * 2 + 1], cp_[nt * 2 + 1]);
            }
        }
    }
    __syncthreads();

    float* srow = g_s[z];
    if (tid < BM) {
        atomicAdd(&srow[grb + tid], rs[tid]);
        if (needCol) {
            float cv = cs[tid];
            int cloc = gcb + tid;
            if (z == 3)      atomicAdd(&g_c[0][cloc], cv);
            else if (z == 4) atomicAdd(&g_c[1][cloc], cv);
            else             atomicAdd(&srow[cloc], cv);  // symmetric fold
        }
    }
}

// ---- final loss: 1024 threads, 4 rows each ----------------------------------
__global__ void __launch_bounds__(1024) loss_kernel(float* __restrict__ out) {
    __shared__ float red[1024];
    float acc = 0.0f;
    #pragma unroll
    for (int it = 0; it < 4; it++) {
        int i = threadIdx.x + it * 1024;
        float d0 = g_d[0][i], s0 = g_s[0][i];
        float d1 = g_d[1][i], s1 = g_s[1][i];
        float d2 = g_d[2][i], s2 = g_s[2][i];
        float d3 = g_d[3][i], s3 = g_s[3][i];
        float d4 = g_d[4][i], s4 = g_s[4][i];
        float c0 = g_c[0][i], c1 = g_c[1][i];
        float denom = (s2 - d2) + (s0 - d0) + (s1 - d1);
        acc += -2.0f * __logf(d2 / denom)
               - __logf(d3 / (s3 - d3)) - __logf(d4 / (s4 - d4))
               - __logf(d3 / (c0 - d3)) - __logf(d4 / (c1 - d4));
    }
    red[threadIdx.x] = acc;
    __syncthreads();
    for (int s = 512; s >= 32; s >>= 1) {
        if (threadIdx.x < s) red[threadIdx.x] += red[threadIdx.x + s];
        __syncthreads();
    }
    if (threadIdx.x < 32) {
        float v = red[threadIdx.x];
        #pragma unroll
        for (int o = 16; o; o >>= 1) v += __shfl_xor_sync(0xffffffffu, v, o);
        if (threadIdx.x == 0) out[0] = v * (1.0f / BSZ);
    }
}

// ---------------------------------------------------------------------------
extern "C" void kernel_launch(void* const* d_in, const int* in_sizes, int n_in,
                              void* d_out, int out_size) {
    const float* x = (const float*)d_in[0];
    (void)in_sizes; (void)n_in; (void)out_size;

    cudaFuncSetAttribute(gemm_kernel, cudaFuncAttributeMaxDynamicSharedMemorySize,
                         SMEM_BYTES);

    normalize_kernel<<<NROWS / 8, 256>>>(x);
    gemm_kernel<<<NBLK, 256, SMEM_BYTES>>>();
    loss_kernel<<<1, 1024>>>((float*)d_out);
}

// round 7
// speedup vs baseline: 7.7280x; 1.0315x over previous
#include <cuda_runtime.h>
#include <cuda_fp16.h>
#include <cstdint>
#include <math.h>

#define NROWS 12288
#define DIM   128
#define BSZ   4096
#define BM    128
#define BN    128
#define NT    32           // 4096 / 128
#define SYMT  528          // 32*33/2
#define NBLK  (2*SYMT + 3*NT*NT)   // 4128

// ---- device scratch --------------------------------------------------------
__device__ __align__(16) __half g_n[NROWS * DIM];  // normalized fp16
__device__ float g_s[5][BSZ];   // row sums (xx, yy, xy, xz, yz)
__device__ float g_c[2][BSZ];   // col sums of xz, yz (== s_zx, s_zy)
__device__ float g_d[5][BSZ];   // diagonals

// ---- helpers ----------------------------------------------------------------
__device__ __forceinline__ uint32_t smem_u32(const void* p) {
    uint32_t a;
    asm("{ .reg .u64 t; cvta.to.shared.u64 t, %1; cvt.u32.u64 %0, t; }"
        : "=r"(a) : "l"(p));
    return a;
}
__device__ __forceinline__ __half2 h2ex2(__half2 a) {
    uint32_t r, x = *(uint32_t*)&a;
    asm("ex2.approx.f16x2 %0, %1;" : "=r"(r) : "r"(x));
    return *(__half2*)&r;
}
__device__ __forceinline__ void cp16(uint32_t dst, const void* src) {
    asm volatile("cp.async.cg.shared.global [%0], [%1], 16;"
                 :: "r"(dst), "l"(src) : "memory");
}
__device__ __forceinline__ void cp_commit() {
    asm volatile("cp.async.commit_group;" ::: "memory");
}
template <int N>
__device__ __forceinline__ void cp_wait() {
    asm volatile("cp.async.wait_group %0;" :: "n"(N) : "memory");
}
__device__ __forceinline__ void ldsm4(uint32_t* r, uint32_t a) {
    asm volatile("ldmatrix.sync.aligned.m8n8.x4.shared.b16 {%0,%1,%2,%3}, [%4];"
                 : "=r"(r[0]), "=r"(r[1]), "=r"(r[2]), "=r"(r[3]) : "r"(a));
}
// fp16-in, fp16-accumulate MMA (packed f16x2 C)
__device__ __forceinline__ void mma16816h(uint32_t* c, const uint32_t* a, const uint32_t* b) {
    asm volatile(
        "mma.sync.aligned.m16n8k16.row.col.f16.f16.f16.f16 "
        "{%0,%1}, {%2,%3,%4,%5}, {%6,%7}, {%0,%1};"
        : "+r"(c[0]), "+r"(c[1])
        : "r"(a[0]), "r"(a[1]), "r"(a[2]), "r"(a[3]), "r"(b[0]), "r"(b[1]));
}

// ---- normalize (+ zero scratch, fused) --------------------------------------
__global__ void normalize_kernel(const float* __restrict__ x) {
    int zi = blockIdx.x * 256 + threadIdx.x;
    if (zi < 5 * BSZ)                ((float*)g_s)[zi] = 0.0f;
    else if (zi < 7 * BSZ)           ((float*)g_c)[zi - 5 * BSZ] = 0.0f;

    int row  = blockIdx.x * 8 + (threadIdx.x >> 5);
    int lane = threadIdx.x & 31;
    float4 v = ((const float4*)(x + (size_t)row * DIM))[lane];
    float ss = fmaf(v.x, v.x, fmaf(v.y, v.y, fmaf(v.z, v.z, v.w * v.w)));
    #pragma unroll
    for (int o = 16; o; o >>= 1) ss += __shfl_xor_sync(0xffffffffu, ss, o);
    float inv = rsqrtf(fmaxf(ss, 1e-24f));

    __half2 h01 = __floats2half2_rn(v.x * inv, v.y * inv);
    __half2 h23 = __floats2half2_rn(v.z * inv, v.w * inv);
    *(uint2*)(g_n + (size_t)row * DIM + lane * 4) =
        make_uint2(*(uint32_t*)&h01, *(uint32_t*)&h23);
}

// ---- main GEMM + fused exp/reduce ------------------------------------------
// dyn smem: A 32K | B 32K | rs 512 | cs 512   (whole K=128 resident)
#define SM_A      0
#define SM_B      32768
#define SM_RS     65536
#define SM_CS     (65536 + 512)
#define SMEM_BYTES (65536 + 1024)

__global__ void __launch_bounds__(256, 3) gemm_kernel() {
    extern __shared__ char sbp[];
    const uint32_t sb = smem_u32(sbp);

    const int tid = threadIdx.x, wid = tid >> 5, lane = tid & 31;

    // block -> (z, by, bx)
    int idx = blockIdx.x;
    int z, by, bx;
    if (idx < 2 * SYMT) {
        z = idx < SYMT ? 0 : 1;
        int t = idx - z * SYMT, r = 0;
        while (t >= NT - r) { t -= NT - r; r++; }
        by = r; bx = r + t;                       // upper triangle incl diag
    } else {
        int t = idx - 2 * SYMT;
        z = 2 + t / (NT * NT); t %= NT * NT;
        by = t / NT; bx = t % NT;
    }
    const int aoffs[5] = {0, 1, 0, 0, 1};
    const int boffs[5] = {0, 1, 1, 2, 2};
    const bool sym      = (z < 2);
    const bool needCol  = (z >= 3) || (sym && bx > by);
    const bool needDiag = (by == bx);

    const char* Agp = (const char*)g_n + (size_t)(aoffs[z] * BSZ + by * BM) * (DIM * 2);
    const char* Bgp = (const char*)g_n + (size_t)(boffs[z] * BSZ + bx * BN) * (DIM * 2);

    // zero reduction scratch BEFORE the mainloop (barriers below cover it)
    float* rs = (float*)(sbp + SM_RS);
    float* cs = (float*)(sbp + SM_CS);
    if (tid < BM) { rs[tid] = 0.0f; cs[tid] = 0.0f; }

    // ---- stage: rows are 256B; swizzle XOR (row&7)<<4 for ldmatrix ---------
    auto stage = [&](int half) {
        int rowQ = tid >> 3, seg = tid & 7;
        #pragma unroll
        for (int it = 0; it < 4; it++) {
            int row = rowQ + it * 32;
            uint32_t off = (uint32_t)(row * 256 + half * 128 + seg * 16);
            uint32_t sw  = off ^ ((row & 7) << 4);
            cp16(sb + SM_A + sw, Agp + off);
            cp16(sb + SM_B + sw, Bgp + off);
        }
        cp_commit();
    };

    const int warp_m = wid >> 2, warp_n = wid & 3;      // 2 x 4 warp grid
    const int rowT = warp_m * 64, colT = warp_n * 32;
    const int lr16 = lane & 15, lcs = (lane >> 4) * 16;

    uint32_t acc[4][4][2];   // packed f16x2
    #pragma unroll
    for (int i = 0; i < 4; i++)
        #pragma unroll
        for (int j = 0; j < 4; j++) { acc[i][j][0] = 0u; acc[i][j][1] = 0u; }

    auto compute = [&](int k16lo, int k16hi) {
        #pragma unroll
        for (int k16 = k16lo; k16 < k16hi; k16++) {
            uint32_t af[4][4], bf[2][4];
            #pragma unroll
            for (int mt = 0; mt < 4; mt++) {
                int row = rowT + mt * 16 + lr16;
                uint32_t off = (uint32_t)(row * 256 + k16 * 32 + lcs);
                ldsm4(af[mt], sb + SM_A + (off ^ ((row & 7) << 4)));
            }
            #pragma unroll
            for (int nb = 0; nb < 2; nb++) {
                int row = colT + nb * 16 + lr16;
                uint32_t off = (uint32_t)(row * 256 + k16 * 32 + lcs);
                ldsm4(bf[nb], sb + SM_B + (off ^ ((row & 7) << 4)));
            }
            #pragma unroll
            for (int mt = 0; mt < 4; mt++)
                #pragma unroll
                for (int nt = 0; nt < 4; nt++) {
                    uint32_t bb[2] = {bf[nt >> 1][nt & 1], bf[nt >> 1][(nt & 1) + 2]};
                    mma16816h(acc[mt][nt], af[mt], bb);
                }
        }
    };

    // ---- mainloop: two K-halves, 2 barriers ----------------------------------
    stage(0);
    stage(1);
    cp_wait<1>(); __syncthreads();
    compute(0, 4);
    cp_wait<0>(); __syncthreads();
    compute(4, 8);

    // ---- epilogue: f16x2 exp + reductions ------------------------------------
    const __half2 SC2 = __float2half2_rn(14.4269504088896340f);  // 10*log2(e)
    const int q = lane >> 2, p2 = (lane & 3) * 2;
    float* dd = g_d[z];
    const int grb = by * BM, gcb = bx * BN;

    float rp[8], cp_[8];
    #pragma unroll
    for (int i = 0; i < 8; i++) { rp[i] = 0.0f; cp_[i] = 0.0f; }

    #pragma unroll
    for (int mt = 0; mt < 4; mt++)
        #pragma unroll
        for (int nt = 0; nt < 4; nt++) {
            __half2 q0 = h2ex2(__hmul2(*(__half2*)&acc[mt][nt][0], SC2));
            __half2 q1 = h2ex2(__hmul2(*(__half2*)&acc[mt][nt][1], SC2));
            float2 f0 = __half22float2(q0);
            float2 f1 = __half22float2(q1);
            rp[mt * 2 + 0] += f0.x + f0.y;
            rp[mt * 2 + 1] += f1.x + f1.y;
            cp_[nt * 2 + 0] += f0.x + f1.x;
            cp_[nt * 2 + 1] += f0.y + f1.y;
            if (needDiag) {
                int r0 = rowT + mt * 16 + q, r1 = r0 + 8;
                int c0 = colT + nt * 8 + p2;
                if (r0 == c0)     dd[grb + r0] = f0.x;
                if (r0 == c0 + 1) dd[grb + r0] = f0.y;
                if (r1 == c0)     dd[grb + r1] = f1.x;
                if (r1 == c0 + 1) dd[grb + r1] = f1.y;
            }
        }

    // row sums: reduce over quad (lanes sharing t/4)
    #pragma unroll
    for (int o = 1; o <= 2; o <<= 1)
        #pragma unroll
        for (int i = 0; i < 8; i++) rp[i] += __shfl_xor_sync(0xffffffffu, rp[i], o);
    if ((lane & 3) == 0) {
        #pragma unroll
        for (int mt = 0; mt < 4; mt++) {
            atomicAdd(&rs[rowT + mt * 16 + q],     rp[mt * 2 + 0]);
            atomicAdd(&rs[rowT + mt * 16 + q + 8], rp[mt * 2 + 1]);
        }
    }
    // col sums: reduce over lanes sharing t%4
    if (needCol) {
        #pragma unroll
        for (int o = 4; o <= 16; o <<= 1)
            #pragma unroll
            for (int i = 0; i < 8; i++) cp_[i] += __shfl_xor_sync(0xffffffffu, cp_[i], o);
        if (lane < 4) {
            #pragma unroll
            for (int nt = 0; nt < 4; nt++) {
                atomicAdd(&cs[colT + nt * 8 + lane * 2],     cp_[nt * 2 + 0]);
                atomicAdd(&cs[colT + nt * 8 + lane * 2 + 1], cp_[nt * 2 + 1]);
            }
        }
    }
    __syncthreads();

    float* srow = g_s[z];
    if (tid < BM) {
        atomicAdd(&srow[grb + tid], rs[tid]);
        if (needCol) {
            float cv = cs[tid];
            int cloc = gcb + tid;
            if (z == 3)      atomicAdd(&g_c[0][cloc], cv);
            else if (z == 4) atomicAdd(&g_c[1][cloc], cv);
            else             atomicAdd(&srow[cloc], cv);  // symmetric fold
        }
    }
}

// ---- final loss: 1024 threads, 4 rows each ----------------------------------
__global__ void __launch_bounds__(1024) loss_kernel(float* __restrict__ out) {
    __shared__ float red[1024];
    float acc = 0.0f;
    #pragma unroll
    for (int it = 0; it < 4; it++) {
        int i = threadIdx.x + it * 1024;
        float d0 = g_d[0][i], s0 = g_s[0][i];
        float d1 = g_d[1][i], s1 = g_s[1][i];
        float d2 = g_d[2][i], s2 = g_s[2][i];
        float d3 = g_d[3][i], s3 = g_s[3][i];
        float d4 = g_d[4][i], s4 = g_s[4][i];
        float c0 = g_c[0][i], c1 = g_c[1][i];
        float denom = (s2 - d2) + (s0 - d0) + (s1 - d1);
        acc += -2.0f * __logf(d2 / denom)
               - __logf(d3 / (s3 - d3)) - __logf(d4 / (s4 - d4))
               - __logf(d3 / (c0 - d3)) - __logf(d4 / (c1 - d4));
    }
    red[threadIdx.x] = acc;
    __syncthreads();
    for (int s = 512; s >= 32; s >>= 1) {
        if (threadIdx.x < s) red[threadIdx.x] += red[threadIdx.x + s];
        __syncthreads();
    }
    if (threadIdx.x < 32) {
        float v = red[threadIdx.x];
        #pragma unroll
        for (int o = 16; o; o >>= 1) v += __shfl_xor_sync(0xffffffffu, v, o);
        if (threadIdx.x == 0) out[0] = v * (1.0f / BSZ);
    }
}

// ---------------------------------------------------------------------------
extern "C" void kernel_launch(void* const* d_in, const int* in_sizes, int n_in,
                              void* d_out, int out_size) {
    const float* x = (const float*)d_in[0];
    (void)in_sizes; (void)n_in; (void)out_size;

    cudaFuncSetAttribute(gemm_kernel, cudaFuncAttributeMaxDynamicSharedMemorySize,
                         SMEM_BYTES);

    normalize_kernel<<<NROWS / 8, 256>>>(x);
    gemm_kernel<<<NBLK, 256, SMEM_BYTES>>>();
    loss_kernel<<<1, 1024>>>((float*)d_out);
}